// round 9
// baseline (speedup 1.0000x reference)
#include <cuda_runtime.h>
#include <cstdint>

// Embedding gather: out[i, :] = table[indices[i], :]
// indices: int32[4194304], table: float32[1000000, 16], out: float32[4194304, 16]
//
// Journal: R4 best (77.9us): 2 threads/row, v8 table loads, streaming stores.
//   R6: L2 evict_last pinning = no-op on this part.
//   R7: per-thread MLP batching regresses (L1tex queue contention).
//   R8: 1 thread/row regresses (L1 wavefronts: no line sharing within warp).
// R4 residual: table DRAM reads 133 MB vs 64 compulsory -> ~50% L2 hit on a
// 64 MB table in 126 MB L2 => quasi-random replacement under stream pressure.
//
// This round: VOCAB-RANGE TILING. Two sequential launches; pass p gathers only
// rows whose index falls in [p*VOCAB/2, (p+1)*VOCAB/2). Hot table set per pass
// = 32 MB (25% of L2) -> much higher hit rate under random replacement, and
// first-touch misses confined to a 32 MB window (better DRAM locality).
// Work shape per active lane identical to R4.

struct __align__(32) f8 { float4 a, b; };

__device__ __forceinline__ f8 ldg_nc_f8(const f8* p) {
    f8 v;
    asm volatile(
        "ld.global.nc.v8.f32 {%0,%1,%2,%3,%4,%5,%6,%7}, [%8];"
        : "=f"(v.a.x), "=f"(v.a.y), "=f"(v.a.z), "=f"(v.a.w),
          "=f"(v.b.x), "=f"(v.b.y), "=f"(v.b.z), "=f"(v.b.w)
        : "l"(p));
    return v;
}

static constexpr int ROW_HALVES = 2;   // 16 floats = 2 x 32 B halves per row

__global__ void __launch_bounds__(256) gather_pass_kernel(
    const int* __restrict__ indices,
    const f8* __restrict__ table8,     // table as 32 B chunks: 2 per row
    float4* __restrict__ out4,
    int total_chunks,
    int lo, int hi)                    // vocab range for this pass
{
    int j = blockIdx.x * blockDim.x + threadIdx.x;   // 32 B chunk id
    if (j >= total_chunks) return;

    int row = j >> 1;          // output row
    int sub = j & 1;           // which 32 B half of the row

    int idx = __ldcs(&indices[row]);
    if (idx < lo || idx >= hi) return;   // other pass handles this row

    f8 v = ldg_nc_f8(&table8[(long long)idx * ROW_HALVES + sub]);

    __stcs(&out4[j * 2 + 0], v.a);
    __stcs(&out4[j * 2 + 1], v.b);
}

extern "C" void kernel_launch(void* const* d_in, const int* in_sizes, int n_in,
                              void* d_out, int out_size)
{
    // Resolve input order by size: indices = 4,194,304 elems, table = 16,000,000.
    int idx_slot = 0, tab_slot = 1;
    if (n_in >= 2 && in_sizes[0] > in_sizes[1]) { idx_slot = 1; tab_slot = 0; }

    const int* indices = (const int*)d_in[idx_slot];
    const f8*  table8  = (const f8*)d_in[tab_slot];
    float4*    out4    = (float4*)d_out;

    int num_indices  = in_sizes[idx_slot];           // 4,194,304
    int vocab        = in_sizes[tab_slot] / 16;      // 1,000,000
    int total_chunks = num_indices * ROW_HALVES;     // 8,388,608

    int threads = 256;
    int blocks  = (total_chunks + threads - 1) / threads;

    // Two vocab-range passes; each pass's hot table slice (32 MB) lives in L2.
    int half = (vocab + 1) / 2;
    gather_pass_kernel<<<blocks, threads>>>(indices, table8, out4,
                                            total_chunks, 0, half);
    gather_pass_kernel<<<blocks, threads>>>(indices, table8, out4,
                                            total_chunks, half, vocab);
}

// round 10
// speedup vs baseline: 1.3739x; 1.3739x over previous
#include <cuda_runtime.h>
#include <cstdint>

// Embedding gather: out[i, :] = table[indices[i], :]
// indices: int32[4194304], table: float32[1000000, 16], out: float32[4194304, 16]
//
// Journal:
//   R4 BEST 77.9us: 2 threads/row, v8 table loads, streaming stores (405MB @ 5.25TB/s).
//   R6 L2 evict_last pinning: no-op on this part.
//   R7 per-thread MLP x4: regressed (L1tex queue contention).
//   R8 1 thread/row: regressed (no line sharing in warp, L1 wavefront bound).
//   R9 vocab tiling: traffic 405->306MB but BW 5.25->2.95TB/s (half-empty
//      warps + partial-line store RMW) -> net regression. Structure levers dead.
//
// This round = R4 + warp-shuffle index dedup: lanes<16 load 16 consecutive
// indices (one 64B transaction per warp), shfl distributes to both half-row
// lanes. Halves index wavefronts; DRAM-visible pattern identical to R4.

struct __align__(32) f8 { float4 a, b; };

__device__ __forceinline__ f8 ldg_nc_f8(const f8* p) {
    f8 v;
    asm volatile(
        "ld.global.nc.v8.f32 {%0,%1,%2,%3,%4,%5,%6,%7}, [%8];"
        : "=f"(v.a.x), "=f"(v.a.y), "=f"(v.a.z), "=f"(v.a.w),
          "=f"(v.b.x), "=f"(v.b.y), "=f"(v.b.z), "=f"(v.b.w)
        : "l"(p));
    return v;
}

static constexpr int ROW_HALVES = 2;   // 16 floats = 2 x 32 B halves per row

__global__ void __launch_bounds__(256) gather_kernel(
    const int* __restrict__ indices,
    const f8* __restrict__ table8,     // table as 32 B chunks: 2 per row
    float4* __restrict__ out4,
    int total_chunks)
{
    int j = blockIdx.x * blockDim.x + threadIdx.x;   // 32 B chunk id
    if (j >= total_chunks) return;

    int lane = threadIdx.x & 31;

    // Warp covers 32 chunks = 16 rows. Lanes 0..15 load the 16 indices
    // (one coalesced 64 B transaction); shfl hands each lane its row's index.
    int warp_row_base = (j - lane) >> 1;             // first row of this warp
    int my_idx_lane   = lane >> 1;                   // row-within-warp
    int loaded = 0;
    if (lane < 16) loaded = __ldcs(&indices[warp_row_base + lane]);
    int idx = __shfl_sync(0xFFFFFFFFu, loaded, my_idx_lane);

    int sub = j & 1;                                 // which 32 B half of row

    f8 v = ldg_nc_f8(&table8[(long long)idx * ROW_HALVES + sub]);

    // Streaming stores: 2x128-bit, fully coalesced across the warp.
    __stcs(&out4[j * 2 + 0], v.a);
    __stcs(&out4[j * 2 + 1], v.b);
}

extern "C" void kernel_launch(void* const* d_in, const int* in_sizes, int n_in,
                              void* d_out, int out_size)
{
    // Resolve input order by size: indices = 4,194,304 elems, table = 16,000,000.
    int idx_slot = 0, tab_slot = 1;
    if (n_in >= 2 && in_sizes[0] > in_sizes[1]) { idx_slot = 1; tab_slot = 0; }

    const int* indices = (const int*)d_in[idx_slot];
    const f8*  table8  = (const f8*)d_in[tab_slot];
    float4*    out4    = (float4*)d_out;

    int num_indices  = in_sizes[idx_slot];           // 4,194,304
    int total_chunks = num_indices * ROW_HALVES;     // 8,388,608

    int threads = 256;
    int blocks  = (total_chunks + threads - 1) / threads;   // 32768
    gather_kernel<<<blocks, threads>>>(indices, table8, out4, total_chunks);
}